// round 12
// baseline (speedup 1.0000x reference)
#include <cuda_runtime.h>

#define NGRAPH 64
#define SPTS   1024
#define TILE   128
#define NTILE  8
#define NPAIRS 36           // tile-pairs per graph (ti <= tj)
#define HIDDEN 256
#define NBINS  64
#define HROWS  66           // 64 bins + dump row + 1 pad row (uint4 init)
#define SLICE  64           // output units per mlp block

typedef unsigned long long ull;

// per-(graph, tile-pair-block) partial histograms; fully overwritten every call
__device__ unsigned int g_part[NGRAPH][NPAIRS][NBINS];
// per-graph arrival counters (zero-init at load; self-reset every call)
__device__ unsigned int g_cnt[NGRAPH];
__device__ unsigned int g_fin[NGRAPH];

// ---------- helpers ----------
__device__ __forceinline__ unsigned smem_u32(const void* p) {
    unsigned a;
    asm("{ .reg .u64 t; cvta.to.shared.u64 t, %1; cvt.u32.u64 %0, t; }" : "=r"(a) : "l"(p));
    return a;
}
__device__ __forceinline__ ull f2_pack(float a, float b) {
    ull r; asm("mov.b64 %0, {%1, %2};" : "=l"(r) : "f"(a), "f"(b)); return r;
}
__device__ __forceinline__ void f2_unpack(ull v, float& a, float& b) {
    asm("mov.b64 {%0, %1}, %2;" : "=f"(a), "=f"(b) : "l"(v));
}
__device__ __forceinline__ ull f2_add(ull a, ull b) {
    ull r; asm("add.rn.f32x2 %0, %1, %2;" : "=l"(r) : "l"(a), "l"(b)); return r;
}
__device__ __forceinline__ ull f2_mul(ull a, ull b) {
    ull r; asm("mul.rn.f32x2 %0, %1, %2;" : "=l"(r) : "l"(a), "l"(b)); return r;
}
__device__ __forceinline__ ull f2_fma(ull a, ull b, ull c) {
    ull r; asm("fma.rn.f32x2 %0, %1, %2, %3;" : "=l"(r) : "l"(a), "l"(b), "l"(c)); return r;
}
__device__ __forceinline__ float fsqrt_approx(float x) {
    float y; asm("sqrt.approx.f32 %0, %1;" : "=f"(y) : "f"(x)); return y;
}

// byte offset of the bin row for scaled squared distance d2 (see R11 notes).
__device__ __forceinline__ unsigned off_of(float d2) {
    float d = fsqrt_approx(d2);
    unsigned v = __float_as_uint(fminf(d, 64.0f) + 8388607.5f);
    v = max(v, 0x4B000000u);
    return v * 256u;
}

// ---------- kernel 1: pairwise histogram (R11 core, early PDL trigger) ----------
__global__ __launch_bounds__(TILE, 8) void hist_kernel(const float* __restrict__ pos) {
    __shared__ __align__(16) unsigned short sh_hist[HROWS * TILE];   // 16896 B
    __shared__ __align__(16) float xs[TILE], ys[TILE], zs[TILE];
    __shared__ unsigned int red_u[TILE];

    // PDL trigger as early as possible: dependent (mlp) grid may launch while
    // hist is still running; mlp self-orders via g_cnt below.
    asm volatile("griddepcontrol.launch_dependents;");

    const int t = threadIdx.x;
    const int g = blockIdx.y;

    int ti = 0, rem = blockIdx.x;
    while (rem >= NTILE - ti) { rem -= NTILE - ti; ++ti; }
    const int tj = ti + rem;

    // uint4 zero-init
    {
        uint4* z = (uint4*)sh_hist;
        const uint4 zero = make_uint4(0, 0, 0, 0);
        #pragma unroll
        for (int i = t; i < HROWS * TILE * 2 / 16; i += TILE) z[i] = zero;
    }

    const float SCALE = 2.56f;   // NUM_BINS / MAX_DIST

    {
        const float* q = pos + ((size_t)(g * SPTS + tj * TILE + t)) * 3;
        xs[t] = q[0] * SCALE; ys[t] = q[1] * SCALE; zs[t] = q[2] * SCALE;
    }
    const float* r = pos + ((size_t)(g * SPTS + ti * TILE + t)) * 3;
    const float xi = r[0] * SCALE, yi = r[1] * SCALE, zi = r[2] * SCALE;
    const ull nxi = f2_pack(-xi, -xi);
    const ull nyi = f2_pack(-yi, -yi);
    const ull nzi = f2_pack(-zi, -zi);

    __syncthreads();

    const ull* X2 = (const ull*)xs;
    const ull* Y2 = (const ull*)ys;
    const ull* Z2 = (const ull*)zs;
    // bank-conflict-free per-thread slot within each 256B row
    char* hb = (char*)sh_hist + (4 * (t & 31) + 128 * ((t >> 5) & 1) + 2 * (t >> 6));

    if (ti != tj) {
        #pragma unroll 8
        for (int h = 0; h < TILE / 2; ++h) {
            ull dx = f2_add(X2[h], nxi);
            ull dy = f2_add(Y2[h], nyi);
            ull dz = f2_add(Z2[h], nzi);
            ull d2 = f2_fma(dx, dx, f2_fma(dy, dy, f2_mul(dz, dz)));
            float a, b; f2_unpack(d2, a, b);
            *(unsigned short*)(hb + off_of(a)) += 1;
            *(unsigned short*)(hb + off_of(b)) += 1;
        }
    } else {
        #pragma unroll 4
        for (int h = 0; h < TILE / 2; ++h) {
            const int j0 = 2 * h;
            ull dx = f2_add(X2[h], nxi);
            ull dy = f2_add(Y2[h], nyi);
            ull dz = f2_add(Z2[h], nzi);
            ull d2 = f2_fma(dx, dx, f2_fma(dy, dy, f2_mul(dz, dz)));
            float a, b; f2_unpack(d2, a, b);
            *(unsigned short*)(hb + off_of(a)) += (unsigned short)(j0 > t ? 1 : 0);
            *(unsigned short*)(hb + off_of(b)) += (unsigned short)(j0 + 1 > t ? 1 : 0);
        }
    }

    __syncthreads();

    // reduce: sum all 128 u16 slots of each bin row (layout-agnostic)
    {
        const unsigned int* H = (const unsigned int*)sh_hist;
        const int b   = t & 63;
        const int seg = t >> 6;
        unsigned s = 0;
        #pragma unroll 8
        for (int a = 0; a < 32; ++a) {
            unsigned w = H[b * 64 + seg * 32 + ((a + b) & 31)];
            s += (w & 0xFFFFu) + (w >> 16);
        }
        red_u[t] = s;
    }
    __syncthreads();
    if (t < NBINS) g_part[g][blockIdx.x][t] = red_u[t] + red_u[t + 64];
    __syncthreads();
    // release: publish this block's partial, then bump the per-graph counter
    if (t == 0) {
        __threadfence();
        atomicAdd(&g_cnt[g], 1u);
    }
}

// ---------- kernel 2: MLP, per-graph early start ----------
__global__ __launch_bounds__(128) void mlp_kernel(const float* __restrict__ W1,
                                                  const float* __restrict__ b1,
                                                  const float* __restrict__ W2,
                                                  const float* __restrict__ b2,
                                                  float* __restrict__ out) {
    extern __shared__ __align__(16) float w2s[];          // 64 KB dynamic
    __shared__ float hn[NBINS];
    __shared__ __align__(16) float act[HIDDEN];
    __shared__ float inv_s;

    const int g = blockIdx.y;
    const int s = blockIdx.x;
    const int t = threadIdx.x;

    // 1. fire W2 slice loads (independent of histogram results)
    {
        const float* src_base = W2 + (size_t)(s * SLICE) * HIDDEN;
        const unsigned sbase = smem_u32(w2s);
        #pragma unroll
        for (int i = 0; i < 32; ++i) {
            int idx = t + 128 * i;                 // 0..4095 float4 chunks
            int u   = idx >> 6;
            int k4  = idx & 63;
            const float* src = src_base + (size_t)u * HIDDEN + k4 * 4;
            unsigned dst = sbase + (unsigned)(u * 256 + (((k4 + u) & 63) << 2)) * 4u;
            asm volatile("cp.async.cg.shared.global [%0], [%1], 16;" :: "r"(dst), "l"(src));
        }
        asm volatile("cp.async.commit_group;");
    }

    // 2. wait for THIS graph's 36 hist blocks (acquire spin, nanosleep backoff)
    if (t == 0) {
        unsigned v;
        while (true) {
            asm volatile("ld.acquire.gpu.global.u32 %0, [%1];"
                         : "=r"(v) : "l"(&g_cnt[g]) : "memory");
            if (v >= NPAIRS) break;
            __nanosleep(128);
        }
    }
    __syncthreads();

    if (t < NBINS) {
        unsigned sum = 0;
        #pragma unroll
        for (int m = 0; m < NPAIRS; ++m) sum += g_part[g][m][t];
        hn[t] = (float)sum;
    }
    __syncthreads();

    // 3. done reading g_part -> arrive; 4th block per graph resets counters
    if (t == 0) {
        unsigned old = atomicAdd(&g_fin[g], 1u);
        if (old == 3u) {                 // all 4 slice-blocks have passed the wait
            g_cnt[g] = 0u;
            g_fin[g] = 0u;
        }
    }

    // 4. total count via warp-0 shuffle reduction (fixed order -> deterministic)
    if (t < 32) {
        float v = hn[t] + hn[t + 32];
        v += __shfl_down_sync(0xffffffffu, v, 16);
        v += __shfl_down_sync(0xffffffffu, v, 8);
        v += __shfl_down_sync(0xffffffffu, v, 4);
        v += __shfl_down_sync(0xffffffffu, v, 2);
        v += __shfl_down_sync(0xffffffffu, v, 1);
        if (t == 0) inv_s = 1.0f / (v + 1e-8f);
    }
    __syncthreads();
    const float inv = inv_s;

    // 5. layer 1: silu(hist_norm @ W1.T + b1), 2 units per thread
    #pragma unroll
    for (int u = t; u < HIDDEN; u += 128) {
        const float4* w = reinterpret_cast<const float4*>(W1 + (size_t)u * NBINS);
        float dot = 0.0f;
        #pragma unroll
        for (int k = 0; k < NBINS / 4; ++k) {
            float4 ww = w[k];
            dot = fmaf(ww.x, hn[4*k+0], dot);
            dot = fmaf(ww.y, hn[4*k+1], dot);
            dot = fmaf(ww.z, hn[4*k+2], dot);
            dot = fmaf(ww.w, hn[4*k+3], dot);
        }
        float x   = fmaf(dot, inv, b1[u]);
        float sig = 1.0f / (1.0f + __expf(-x));
        act[u] = x * sig;
    }
    asm volatile("cp.async.wait_group 0;" ::: "memory");
    __syncthreads();

    // 6. layer 2: one thread per unit, all-smem FMA, diagonal-swizzled reads
    if (t < SLICE) {
        const int u = t;
        const float4* av = reinterpret_cast<const float4*>(act);
        float acc = b2[s * SLICE + u];
        #pragma unroll 8
        for (int k = 0; k < 64; ++k) {
            const float4 w = *reinterpret_cast<const float4*>(w2s + u * 256 + (((k + u) & 63) << 2));
            const float4 a = av[k];
            acc = fmaf(w.x, a.x, acc);
            acc = fmaf(w.y, a.y, acc);
            acc = fmaf(w.z, a.z, acc);
            acc = fmaf(w.w, a.w, acc);
        }
        out[(size_t)g * HIDDEN + s * SLICE + u] = acc;
    }
}

extern "C" void kernel_launch(void* const* d_in, const int* in_sizes, int n_in,
                              void* d_out, int out_size) {
    // Size-based input ID: pos=196608, W1=16384, W2=first 65536 (batch i32 comes
    // later), b1/b2 = 256 in order.
    int iPos = 0, iW1 = 1, ib1 = 2, iW2 = 3, ib2 = 4;
    {
        int fp = -1, f1 = -1, f2v = -1, fb1 = -1, fb2 = -1;
        for (int i = 0; i < n_in; ++i) {
            int sz = in_sizes[i];
            if (sz == 196608 && fp < 0) fp = i;
            else if (sz == 16384 && f1 < 0) f1 = i;
            else if (sz == 65536 && f2v < 0) f2v = i;
            else if (sz == 256) { if (fb1 < 0) fb1 = i; else if (fb2 < 0) fb2 = i; }
        }
        if (fp >= 0 && f1 >= 0 && f2v >= 0 && fb1 >= 0 && fb2 >= 0) {
            iPos = fp; iW1 = f1; iW2 = f2v; ib1 = fb1; ib2 = fb2;
        }
    }
    const float* pos = (const float*)d_in[iPos];
    const float* W1  = (const float*)d_in[iW1];
    const float* b1  = (const float*)d_in[ib1];
    const float* W2  = (const float*)d_in[iW2];
    const float* b2  = (const float*)d_in[ib2];
    float* out = (float*)d_out;

    const int dyn = SLICE * HIDDEN * (int)sizeof(float);   // 64 KB
    static bool configured = false;
    if (!configured) {
        cudaFuncSetAttribute(mlp_kernel, cudaFuncAttributeMaxDynamicSharedMemorySize, dyn);
        configured = true;
    }

    hist_kernel<<<dim3(NPAIRS, NGRAPH), TILE>>>(pos);

    // PDL launch: mlp may start mid-hist; per-graph g_cnt spin provides the
    // actual data dependency.
    cudaLaunchConfig_t cfg = {};
    cfg.gridDim  = dim3(4, NGRAPH);
    cfg.blockDim = dim3(128);
    cfg.dynamicSmemBytes = dyn;
    cfg.stream = 0;
    cudaLaunchAttribute attrs[1];
    attrs[0].id = cudaLaunchAttributeProgrammaticStreamSerialization;
    attrs[0].val.programmaticStreamSerializationAllowed = 1;
    cfg.attrs = attrs;
    cfg.numAttrs = 1;
    cudaLaunchKernelEx(&cfg, mlp_kernel, W1, b1, W2, b2, out);
}

// round 13
// speedup vs baseline: 1.0502x; 1.0502x over previous
#include <cuda_runtime.h>

#define NGRAPH 64
#define SPTS   1024
#define TILE   128
#define NTILE  8
#define NPAIRS 36           // tile-pairs per graph (ti <= tj)
#define HIDDEN 256
#define NBINS  64
#define HROWS  66           // 64 bins + dump row + 1 pad row (uint4 init)
#define SLICE  64           // output units per mlp block

typedef unsigned long long ull;

// per-(graph, tile-pair-block) partial histograms; fully overwritten every call
__device__ unsigned int g_part[NGRAPH][NPAIRS][NBINS];

// ---------- helpers ----------
__device__ __forceinline__ unsigned smem_u32(const void* p) {
    unsigned a;
    asm("{ .reg .u64 t; cvta.to.shared.u64 t, %1; cvt.u32.u64 %0, t; }" : "=r"(a) : "l"(p));
    return a;
}
__device__ __forceinline__ ull f2_pack(float a, float b) {
    ull r; asm("mov.b64 %0, {%1, %2};" : "=l"(r) : "f"(a), "f"(b)); return r;
}
__device__ __forceinline__ void f2_unpack(ull v, float& a, float& b) {
    asm("mov.b64 {%0, %1}, %2;" : "=f"(a), "=f"(b) : "l"(v));
}
__device__ __forceinline__ ull f2_add(ull a, ull b) {
    ull r; asm("add.rn.f32x2 %0, %1, %2;" : "=l"(r) : "l"(a), "l"(b)); return r;
}
__device__ __forceinline__ ull f2_mul(ull a, ull b) {
    ull r; asm("mul.rn.f32x2 %0, %1, %2;" : "=l"(r) : "l"(a), "l"(b)); return r;
}
__device__ __forceinline__ ull f2_fma(ull a, ull b, ull c) {
    ull r; asm("fma.rn.f32x2 %0, %1, %2, %3;" : "=l"(r) : "l"(a), "l"(b), "l"(c)); return r;
}
__device__ __forceinline__ float fsqrt_approx(float x) {
    float y; asm("sqrt.approx.f32 %0, %1;" : "=f"(y) : "f"(x)); return y;
}

// byte offset of the bin row for scaled squared distance d2.
// v = bits(fmin(sqrt(d2),64) + (2^23-0.5)) = 0x4B000000 + k (clamped for the
// d in (0,0.25) round-down case). Row stride 256 B; 0x4B000000*256 wraps to 0
// mod 2^32, so off = v*256 = k*256 exactly. k <= 64 (dump row).
__device__ __forceinline__ unsigned off_of(float d2) {
    float d = fsqrt_approx(d2);
    unsigned v = __float_as_uint(fminf(d, 64.0f) + 8388607.5f);
    v = max(v, 0x4B000000u);
    return v * 256u;
}

// ---------- kernel 1: pairwise histogram ----------
// grid = (36 tile-pairs, 64 graphs), block = 128 threads.
// Off-diagonal (28/36): R11 core — thread t = row i, f2x2 sweep of 128 cols,
//   every slot a valid pair.
// Diagonal (8/36): circular-offset enumeration — thread t covers pairs
//   (t, t+c mod 128) for c=1..64 (c=64 only for t<64, as a 0/1 increment):
//   64 uniform slots for 8128 pairs instead of 128 predicated slots.
// Counts in per-thread u16 slots; each WARP covers 32 distinct banks.
__global__ __launch_bounds__(TILE, 8) void hist_kernel(const float* __restrict__ pos) {
    __shared__ __align__(16) unsigned short sh_hist[HROWS * TILE];   // 16896 B
    __shared__ __align__(16) float xs[192], ys[192], zs[192];        // 192: mod-free diag
    __shared__ unsigned int red_u[TILE];

    const int t = threadIdx.x;
    const int g = blockIdx.y;

    int ti = 0, rem = blockIdx.x;
    while (rem >= NTILE - ti) { rem -= NTILE - ti; ++ti; }
    const int tj = ti + rem;

    // uint4 zero-init
    {
        uint4* z = (uint4*)sh_hist;
        const uint4 zero = make_uint4(0, 0, 0, 0);
        #pragma unroll
        for (int i = t; i < HROWS * TILE * 2 / 16; i += TILE) z[i] = zero;
    }

    const float SCALE = 2.56f;   // NUM_BINS / MAX_DIST

    {
        const float* q = pos + ((size_t)(g * SPTS + tj * TILE + t)) * 3;
        float qx = q[0] * SCALE, qy = q[1] * SCALE, qz = q[2] * SCALE;
        xs[t] = qx; ys[t] = qy; zs[t] = qz;
        if (t < 64) { xs[128 + t] = qx; ys[128 + t] = qy; zs[128 + t] = qz; }
    }
    const float* r = pos + ((size_t)(g * SPTS + ti * TILE + t)) * 3;
    const float xi = r[0] * SCALE, yi = r[1] * SCALE, zi = r[2] * SCALE;

    __syncthreads();

    // bank-conflict-free per-thread slot within each 256B row
    char* hb = (char*)sh_hist + (4 * (t & 31) + 128 * ((t >> 5) & 1) + 2 * (t >> 6));

    if (ti != tj) {
        const ull nxi = f2_pack(-xi, -xi);
        const ull nyi = f2_pack(-yi, -yi);
        const ull nzi = f2_pack(-zi, -zi);
        const ull* X2 = (const ull*)xs;
        const ull* Y2 = (const ull*)ys;
        const ull* Z2 = (const ull*)zs;
        #pragma unroll 8
        for (int h = 0; h < TILE / 2; ++h) {
            ull dx = f2_add(X2[h], nxi);
            ull dy = f2_add(Y2[h], nyi);
            ull dz = f2_add(Z2[h], nzi);
            ull d2 = f2_fma(dx, dx, f2_fma(dy, dy, f2_mul(dz, dz)));
            float a, b; f2_unpack(d2, a, b);
            *(unsigned short*)(hb + off_of(a)) += 1;
            *(unsigned short*)(hb + off_of(b)) += 1;
        }
    } else {
        // diagonal: pairs (t, t+c) for c = 1..64; c = 64 counts only for t < 64
        const unsigned short incLast = (unsigned short)(t < 64 ? 1 : 0);
        #pragma unroll 8
        for (int c = 1; c <= 64; ++c) {
            const int j = t + c;                   // <= 191, mod-free via duplication
            float dx = xs[j] - xi;
            float dy = ys[j] - yi;
            float dz = zs[j] - zi;
            float d2 = fmaf(dx, dx, fmaf(dy, dy, dz * dz));
            unsigned short inc = (c < 64) ? (unsigned short)1 : incLast;
            *(unsigned short*)(hb + off_of(d2)) += inc;
        }
    }

    __syncthreads();

    // reduce: sum all 128 u16 slots of each bin row (layout-agnostic)
    {
        const unsigned int* H = (const unsigned int*)sh_hist;
        const int b   = t & 63;
        const int seg = t >> 6;
        unsigned s = 0;
        #pragma unroll 8
        for (int a = 0; a < 32; ++a) {
            unsigned w = H[b * 64 + seg * 32 + ((a + b) & 31)];
            s += (w & 0xFFFFu) + (w >> 16);
        }
        red_u[t] = s;
    }
    __syncthreads();
    if (t < NBINS) g_part[g][blockIdx.x][t] = red_u[t] + red_u[t + 64];
    __syncthreads();
    // PDL: partials for this block published -> allow dependent (mlp) scheduling
    if (t == 0) {
        __threadfence();
        asm volatile("griddepcontrol.launch_dependents;");
    }
}

// ---------- kernel 2: MLP, PDL secondary with early async W2 preload (R11) ----------
__global__ __launch_bounds__(128) void mlp_kernel(const float* __restrict__ W1,
                                                  const float* __restrict__ b1,
                                                  const float* __restrict__ W2,
                                                  const float* __restrict__ b2,
                                                  float* __restrict__ out) {
    extern __shared__ __align__(16) float w2s[];          // 64 KB dynamic
    __shared__ float hn[NBINS];
    __shared__ __align__(16) float act[HIDDEN];
    __shared__ float inv_s;

    const int g = blockIdx.y;
    const int s = blockIdx.x;
    const int t = threadIdx.x;

    // 1. fire W2 slice loads (independent of histogram results)
    {
        const float* src_base = W2 + (size_t)(s * SLICE) * HIDDEN;
        const unsigned sbase = smem_u32(w2s);
        #pragma unroll
        for (int i = 0; i < 32; ++i) {
            int idx = t + 128 * i;                 // 0..4095 float4 chunks
            int u   = idx >> 6;
            int k4  = idx & 63;
            const float* src = src_base + (size_t)u * HIDDEN + k4 * 4;
            unsigned dst = sbase + (unsigned)(u * 256 + (((k4 + u) & 63) << 2)) * 4u;
            asm volatile("cp.async.cg.shared.global [%0], [%1], 16;" :: "r"(dst), "l"(src));
        }
        asm volatile("cp.async.commit_group;");
    }

    // 2. wait for primary grid's g_part to be complete & visible
    asm volatile("griddepcontrol.wait;" ::: "memory");

    if (t < NBINS) {
        unsigned sum = 0;
        #pragma unroll
        for (int m = 0; m < NPAIRS; ++m) sum += g_part[g][m][t];
        hn[t] = (float)sum;
    }
    __syncthreads();

    // 3. total count via warp-0 shuffle reduction (fixed order -> deterministic)
    if (t < 32) {
        float v = hn[t] + hn[t + 32];
        v += __shfl_down_sync(0xffffffffu, v, 16);
        v += __shfl_down_sync(0xffffffffu, v, 8);
        v += __shfl_down_sync(0xffffffffu, v, 4);
        v += __shfl_down_sync(0xffffffffu, v, 2);
        v += __shfl_down_sync(0xffffffffu, v, 1);
        if (t == 0) inv_s = 1.0f / (v + 1e-8f);
    }
    __syncthreads();
    const float inv = inv_s;

    // 4. layer 1: silu(hist_norm @ W1.T + b1), 2 units per thread
    #pragma unroll
    for (int u = t; u < HIDDEN; u += 128) {
        const float4* w = reinterpret_cast<const float4*>(W1 + (size_t)u * NBINS);
        float dot = 0.0f;
        #pragma unroll
        for (int k = 0; k < NBINS / 4; ++k) {
            float4 ww = w[k];
            dot = fmaf(ww.x, hn[4*k+0], dot);
            dot = fmaf(ww.y, hn[4*k+1], dot);
            dot = fmaf(ww.z, hn[4*k+2], dot);
            dot = fmaf(ww.w, hn[4*k+3], dot);
        }
        float x   = fmaf(dot, inv, b1[u]);
        float sig = 1.0f / (1.0f + __expf(-x));
        act[u] = x * sig;
    }
    asm volatile("cp.async.wait_group 0;" ::: "memory");
    __syncthreads();

    // 5. layer 2: one thread per unit, all-smem FMA, diagonal-swizzled reads
    if (t < SLICE) {
        const int u = t;
        const float4* av = reinterpret_cast<const float4*>(act);
        float acc = b2[s * SLICE + u];
        #pragma unroll 8
        for (int k = 0; k < 64; ++k) {
            const float4 w = *reinterpret_cast<const float4*>(w2s + u * 256 + (((k + u) & 63) << 2));
            const float4 a = av[k];
            acc = fmaf(w.x, a.x, acc);
            acc = fmaf(w.y, a.y, acc);
            acc = fmaf(w.z, a.z, acc);
            acc = fmaf(w.w, a.w, acc);
        }
        out[(size_t)g * HIDDEN + s * SLICE + u] = acc;
    }
}

extern "C" void kernel_launch(void* const* d_in, const int* in_sizes, int n_in,
                              void* d_out, int out_size) {
    // Size-based input ID: pos=196608, W1=16384, W2=first 65536 (batch i32 comes
    // later), b1/b2 = 256 in order.
    int iPos = 0, iW1 = 1, ib1 = 2, iW2 = 3, ib2 = 4;
    {
        int fp = -1, f1 = -1, f2v = -1, fb1 = -1, fb2 = -1;
        for (int i = 0; i < n_in; ++i) {
            int sz = in_sizes[i];
            if (sz == 196608 && fp < 0) fp = i;
            else if (sz == 16384 && f1 < 0) f1 = i;
            else if (sz == 65536 && f2v < 0) f2v = i;
            else if (sz == 256) { if (fb1 < 0) fb1 = i; else if (fb2 < 0) fb2 = i; }
        }
        if (fp >= 0 && f1 >= 0 && f2v >= 0 && fb1 >= 0 && fb2 >= 0) {
            iPos = fp; iW1 = f1; iW2 = f2v; ib1 = fb1; ib2 = fb2;
        }
    }
    const float* pos = (const float*)d_in[iPos];
    const float* W1  = (const float*)d_in[iW1];
    const float* b1  = (const float*)d_in[ib1];
    const float* W2  = (const float*)d_in[iW2];
    const float* b2  = (const float*)d_in[ib2];
    float* out = (float*)d_out;

    const int dyn = SLICE * HIDDEN * (int)sizeof(float);   // 64 KB
    static bool configured = false;
    if (!configured) {
        cudaFuncSetAttribute(mlp_kernel, cudaFuncAttributeMaxDynamicSharedMemorySize, dyn);
        configured = true;
    }

    hist_kernel<<<dim3(NPAIRS, NGRAPH), TILE>>>(pos);

    cudaLaunchConfig_t cfg = {};
    cfg.gridDim  = dim3(4, NGRAPH);
    cfg.blockDim = dim3(128);
    cfg.dynamicSmemBytes = dyn;
    cfg.stream = 0;
    cudaLaunchAttribute attrs[1];
    attrs[0].id = cudaLaunchAttributeProgrammaticStreamSerialization;
    attrs[0].val.programmaticStreamSerializationAllowed = 1;
    cfg.attrs = attrs;
    cfg.numAttrs = 1;
    cudaLaunchKernelEx(&cfg, mlp_kernel, W1, b1, W2, b2, out);
}